// round 13
// baseline (speedup 1.0000x reference)
#include <cuda_runtime.h>
#include <cuda_bf16.h>
#include <cstdint>

#define NROWS 16384
#define KNBR  32
#define DIN   256
#define DCAT  512

// ---------------- scratch (no allocation allowed -> device globals) ----------
__device__ __nv_bfloat16 g_inh[NROWS * 256], g_inl[NROWS * 256];
__device__ __nv_bfloat16 g_Mth[256 * 256],  g_Mtl[256 * 256];
__device__ __nv_bfloat16 g_Wioh[256 * 256], g_Wiol[256 * 256];
__device__ __nv_bfloat16 g_Wnvh[256 * 256], g_Wnvl[256 * 256];
__device__ __nv_bfloat16 g_Wgh[512 * 512],  g_Wgl[512 * 512];
__device__ __nv_bfloat16 g_ctxh[NROWS * 256], g_ctxl[NROWS * 256];
__device__ __nv_bfloat16 g_o2h[NROWS * 512],  g_o2l[NROWS * 512];
__device__ float g_bqk[256];               // (Wk^T bq)
__device__ float g_veb[256];               // (Wq^T bk)
__device__ float g_bnv[256];               // Wno@bv + bno
__device__ float g_ceb;                    // bq . bk
__device__ float g_qt[NROWS * 256];        // input @ Mt^T + bqk   (fp32)
__device__ float g_part[128 * 512 * 2];    // BN partial sums
__device__ float g_mean[512];
__device__ float g_scale[512];

// ---------------- helpers -----------------------------------------------------
__device__ __forceinline__ void bsplit(float x, __nv_bfloat16& h, __nv_bfloat16& l) {
    h = __float2bfloat16_rn(x);
    l = __float2bfloat16_rn(x - __bfloat162float(h));
}
__device__ __forceinline__ uint32_t packbf2(__nv_bfloat16 a, __nv_bfloat16 b) {
    __nv_bfloat162 p(a, b);
    return *reinterpret_cast<uint32_t*>(&p);
}
__device__ __forceinline__ void cp16(uint32_t s, const void* g) {
    asm volatile("cp.async.cg.shared.global [%0], [%1], 16;\n" :: "r"(s), "l"(g));
}
__device__ __forceinline__ void mma16816(float* c, const uint32_t* a, const uint32_t* b) {
    asm volatile(
        "mma.sync.aligned.m16n8k16.row.col.f32.bf16.bf16.f32 "
        "{%0,%1,%2,%3},{%4,%5,%6,%7},{%8,%9},{%0,%1,%2,%3};\n"
        : "+f"(c[0]), "+f"(c[1]), "+f"(c[2]), "+f"(c[3])
        : "r"(a[0]), "r"(a[1]), "r"(a[2]), "r"(a[3]), "r"(b[0]), "r"(b[1]));
}
__device__ __forceinline__ void ldsm4(uint32_t addr, uint32_t& r0, uint32_t& r1,
                                      uint32_t& r2, uint32_t& r3) {
    asm volatile("ldmatrix.sync.aligned.m8n8.x4.shared.b16 {%0,%1,%2,%3}, [%4];"
                 : "=r"(r0), "=r"(r1), "=r"(r2), "=r"(r3) : "r"(addr));
}

// ---------------- prep: fold weights + biases (bf16 hi/lo) -------------------
__global__ void prep_all(const float* __restrict__ Wq, const float* __restrict__ Wk,
                         const float* __restrict__ Wno, const float* __restrict__ Wv,
                         const float* __restrict__ bq, const float* __restrict__ bk,
                         const float* __restrict__ bv, const float* __restrict__ bno) {
    int b = blockIdx.x, t = threadIdx.x;
    if (b < 256) {
        int i = b; float acc = 0.f;
        for (int o = 0; o < 256; ++o) acc += Wk[o * 256 + i] * Wq[o * 256 + t];
        __nv_bfloat16 h, l; bsplit(acc, h, l);
        g_Mth[i * 256 + t] = h; g_Mtl[i * 256 + t] = l;
    } else if (b < 512) {
        int o = b - 256; float acc = 0.f;
        for (int d = 0; d < 256; ++d) acc += Wno[o * 256 + d] * Wv[d * 256 + t];
        __nv_bfloat16 h, l; bsplit(acc, h, l);
        g_Wnvh[o * 256 + t] = h; g_Wnvl[o * 256 + t] = l;
    } else if (b == 512) {
        float a = 0.f;
        for (int o = 0; o < 256; ++o) a += bq[o] * Wk[o * 256 + t];
        g_bqk[t] = a;
    } else if (b == 513) {
        float a = 0.f;
        for (int o = 0; o < 256; ++o) a += bk[o] * Wq[o * 256 + t];
        g_veb[t] = a;
    } else if (b == 514) {
        float a = 0.f;
        for (int d = 0; d < 256; ++d) a += Wno[t * 256 + d] * bv[d];
        g_bnv[t] = a + bno[t];
    } else if (t == 0) {
        float a = 0.f;
        for (int o = 0; o < 256; ++o) a += bq[o] * bk[o];
        g_ceb = a;
    }
}

// ---------------- split input / Wio / Wg into bf16 hi+lo ---------------------
__global__ void __launch_bounds__(256) split_all(const float* __restrict__ in,
                                                 const float* __restrict__ wio,
                                                 const float* __restrict__ wg) {
    const int b = blockIdx.x, t = threadIdx.x;
    const float* src; __nv_bfloat16 *dh, *dl; int idx;
    if (b < 4096)      { src = in;  dh = g_inh;  dl = g_inl;  idx = b * 256 + t; }
    else if (b < 4160) { src = wio; dh = g_Wioh; dl = g_Wiol; idx = (b - 4096) * 256 + t; }
    else               { src = wg;  dh = g_Wgh;  dl = g_Wgl;  idx = (b - 4160) * 256 + t; }
    float4 v = ((const float4*)src)[idx];
    __nv_bfloat16 h0, l0, h1, l1, h2, l2, h3, l3;
    bsplit(v.x, h0, l0); bsplit(v.y, h1, l1);
    bsplit(v.z, h2, l2); bsplit(v.w, h3, l3);
    uint2 H, L;
    H.x = packbf2(h0, h1); H.y = packbf2(h2, h3);
    L.x = packbf2(l0, l1); L.y = packbf2(l2, l3);
    ((uint2*)dh)[idx] = H;
    ((uint2*)dl)[idx] = L;
}

// ---------------- bf16x3 tensor-core GEMM (ldmatrix + ILP-ordered MMAs) ------
// C[m, coff+n] = A[m,:K] . W[n,:K] + bias[n], A = Ah+Al, W = Wh+Wl (bf16 split).
// MODE 0: fp32 C. MODE 1: bf16 hi/lo out2 + BN column partials (no fp32 C).
// MODE 2: fused final  out = relu(gemm+bias) * relu(bn(o2h+o2l)).

template <int MODE>
__global__ void __launch_bounds__(256, 2) bmma_gemm(
    const __nv_bfloat16* __restrict__ Ah, const __nv_bfloat16* __restrict__ Al,
    const __nv_bfloat16* __restrict__ Wh, const __nv_bfloat16* __restrict__ Wl,
    const float* __restrict__ bias, float* __restrict__ C,
    int K, int ldc, int coff,
    const float* __restrict__ gamma, const float* __restrict__ beta,
    float* __restrict__ outp)
{
    extern __shared__ uint32_t sm[];   // [2 stages][Ah|Al|Wh|Wl], tile=128x20 u32

    const int tid = threadIdx.x;
    const int lane = tid & 31, warp = tid >> 5;
    const int wm = warp >> 2, wn = warp & 3;
    const int g = lane >> 2, tg = lane & 3;
    const int m0 = blockIdx.y * 128, n0 = blockIdx.x * 128;
    const uint32_t sbase = (uint32_t)__cvta_generic_to_shared(sm);

    // ldmatrix lane addressing
    const int lr = lane & 7;           // row within 8x8
    const int lh = (lane >> 3) & 1;
    const int lq = (lane >> 4) & 1;
    uint32_t aAddr[4];                 // A 16x16 tile per mf (x4: rows, rows+8, khi)
#pragma unroll
    for (int mf = 0; mf < 4; ++mf) {
        const int row = wm * 64 + mf * 16 + lr + lh * 8;
        aAddr[mf] = sbase + 4u * (row * 20 + lq * 4);
    }
    uint32_t bAddr[2];                 // two nf per x4 (nf=2p+lq), k-half = lh
#pragma unroll
    for (int p = 0; p < 2; ++p) {
        const int row = wn * 32 + (2 * p + lq) * 8 + lr;
        bAddr[p] = sbase + 4u * (5120 + row * 20 + lh * 4);
    }

    float acc[4][4][4];
#pragma unroll
    for (int i = 0; i < 4; ++i)
#pragma unroll
        for (int j = 0; j < 4; ++j)
#pragma unroll
            for (int h = 0; h < 4; ++h) acc[i][j][h] = 0.f;

    const int nt = K >> 5;

#define ISSUE_TILE(T, BUF)                                                         \
    {                                                                              \
        _Pragma("unroll")                                                          \
        for (int i = 0; i < 2; ++i) {                                              \
            const int id = tid + 256 * i;                                          \
            const int r = id >> 2, cc = id & 3;                                    \
            const uint32_t drow = (uint32_t)(r * 80 + cc * 16 + (BUF) * 40960);    \
            const size_t acol = (size_t)(T) * 32 + cc * 8;                         \
            cp16(sbase + drow,         Ah + (size_t)(m0 + r) * K + acol);          \
            cp16(sbase + drow + 10240, Al + (size_t)(m0 + r) * K + acol);          \
            cp16(sbase + drow + 20480, Wh + (size_t)(n0 + r) * K + acol);          \
            cp16(sbase + drow + 30720, Wl + (size_t)(n0 + r) * K + acol);          \
        }                                                                          \
        asm volatile("cp.async.commit_group;\n");                                  \
    }

    ISSUE_TILE(0, 0);
    asm volatile("cp.async.wait_group 0;\n");
    __syncthreads();

    for (int t = 0; t < nt; ++t) {
        const int buf = t & 1;
        if (t + 1 < nt) ISSUE_TILE(t + 1, buf ^ 1);
        const uint32_t stg = (uint32_t)buf * 40960u;
#pragma unroll
        for (int ks = 0; ks < 2; ++ks) {
            const uint32_t koff = stg + 32u * ks;
            uint32_t bh[4][2], bl[4][2];
            ldsm4(bAddr[0] + koff,          bh[0][0], bh[0][1], bh[1][0], bh[1][1]);
            ldsm4(bAddr[1] + koff,          bh[2][0], bh[2][1], bh[3][0], bh[3][1]);
            ldsm4(bAddr[0] + koff + 10240u, bl[0][0], bl[0][1], bl[1][0], bl[1][1]);
            ldsm4(bAddr[1] + koff + 10240u, bl[2][0], bl[2][1], bl[3][0], bl[3][1]);
#pragma unroll
            for (int mf = 0; mf < 4; ++mf) {
                uint32_t ah[4], al[4];
                ldsm4(aAddr[mf] + koff,          ah[0], ah[1], ah[2], ah[3]);
                ldsm4(aAddr[mf] + koff + 10240u, al[0], al[1], al[2], al[3]);
                // ILP ordering: consecutive MMAs always target different accs;
                // same-acc reuse distance = 4 issues (was 1).
#pragma unroll
                for (int nf = 0; nf < 4; ++nf)
                    mma16816(acc[mf][nf], ah, bh[nf]);
#pragma unroll
                for (int nf = 0; nf < 4; ++nf)
                    mma16816(acc[mf][nf], al, bh[nf]);
#pragma unroll
                for (int nf = 0; nf < 4; ++nf)
                    mma16816(acc[mf][nf], ah, bl[nf]);
            }
        }
        if (t + 1 < nt) {
            asm volatile("cp.async.wait_group 0;\n");
            __syncthreads();
        }
    }
#undef ISSUE_TILE

    // ---------------- epilogue ----------------
    float ps[4][2], pq[4][2];
#pragma unroll
    for (int nf = 0; nf < 4; ++nf) { ps[nf][0]=ps[nf][1]=pq[nf][0]=pq[nf][1]=0.f; }

#pragma unroll
    for (int mf = 0; mf < 4; ++mf) {
        const int r0 = m0 + wm * 64 + mf * 16 + g;
#pragma unroll
        for (int nf = 0; nf < 4; ++nf) {
            const int c = n0 + wn * 32 + nf * 8 + 2 * tg;
            const float b0 = bias[c], b1 = bias[c + 1];
#pragma unroll
            for (int h = 0; h < 2; ++h) {
                const int r = r0 + 8 * h;
                float v0 = acc[mf][nf][2 * h + 0] + b0;
                float v1 = acc[mf][nf][2 * h + 1] + b1;
                if (MODE == 0) {
                    *(float2*)&C[(size_t)r * ldc + coff + c] = make_float2(v0, v1);
                } else if (MODE == 1) {
                    __nv_bfloat16 h0, l0, h1, l1;
                    bsplit(v0, h0, l0); bsplit(v1, h1, l1);
                    *(uint32_t*)&g_o2h[(size_t)r * 512 + coff + c] = packbf2(h0, h1);
                    *(uint32_t*)&g_o2l[(size_t)r * 512 + coff + c] = packbf2(l0, l1);
                    ps[nf][0] += v0; ps[nf][1] += v1;
                    pq[nf][0] += v0 * v0; pq[nf][1] += v1 * v1;
                } else {
                    const int cc = c;  // coff==0 for gate
                    uint32_t uh = *(const uint32_t*)&g_o2h[(size_t)r * 512 + cc];
                    uint32_t ul = *(const uint32_t*)&g_o2l[(size_t)r * 512 + cc];
                    __nv_bfloat162 hh = *reinterpret_cast<__nv_bfloat162*>(&uh);
                    __nv_bfloat162 ll = *reinterpret_cast<__nv_bfloat162*>(&ul);
                    float o0 = __bfloat162float(hh.x) + __bfloat162float(ll.x);
                    float o1 = __bfloat162float(hh.y) + __bfloat162float(ll.y);
                    float bn0 = gamma[cc] * (o0 - g_mean[cc]) * g_scale[cc] + beta[cc];
                    float bn1 = gamma[cc+1] * (o1 - g_mean[cc+1]) * g_scale[cc+1] + beta[cc+1];
                    float2 res = make_float2(fmaxf(v0, 0.f) * fmaxf(bn0, 0.f),
                                             fmaxf(v1, 0.f) * fmaxf(bn1, 0.f));
                    *(float2*)&outp[(size_t)r * 512 + cc] = res;
                }
            }
        }
    }

    if (MODE == 1) {
        __syncthreads();
        float* sbn = (float*)sm;   // [2 wm][128 col][2]
#pragma unroll
        for (int nf = 0; nf < 4; ++nf)
#pragma unroll
            for (int j = 0; j < 2; ++j) {
                float s = ps[nf][j], q = pq[nf][j];
#pragma unroll
                for (int o = 4; o < 32; o <<= 1) {
                    s += __shfl_xor_sync(0xffffffffu, s, o);
                    q += __shfl_xor_sync(0xffffffffu, q, o);
                }
                if (g == 0) {
                    const int col = wn * 32 + nf * 8 + 2 * tg + j;
                    sbn[(wm * 128 + col) * 2 + 0] = s;
                    sbn[(wm * 128 + col) * 2 + 1] = q;
                }
            }
        __syncthreads();
        if (tid < 256) {
            const int col = tid >> 1, q = tid & 1;
            const float tot = sbn[col * 2 + q] + sbn[(128 + col) * 2 + q];
            g_part[((size_t)(m0 >> 7) * 512 + coff + n0 + col) * 2 + q] = tot;
        }
    }
}

// ---------------- pipelined attention: 8 n/CTA, 3-stage cp.async -------------
// stage = nb(8192f) + qt(256f) + input row(256f) = 8704 f = 34816 B, x3 stages.
#define ATTN_NPER 8
#define STG_F 8704
#define STG_B 34816

__device__ __forceinline__ void attn_issue(uint32_t sb, const float* __restrict__ nb,
                                           const float* __restrict__ in,
                                           int n, int buf, int tid) {
    const uint32_t base = sb + (uint32_t)buf * STG_B;
    const float* src = nb + (size_t)n * 8192 + tid * 4;
#pragma unroll
    for (int i = 0; i < 8; ++i)
        cp16(base + (uint32_t)tid * 16 + i * 4096, src + i * 1024);
    if (tid < 64)
        cp16(base + 32768 + (uint32_t)tid * 16, g_qt + (size_t)n * 256 + tid * 4);
    else if (tid < 128)
        cp16(base + 33792 + (uint32_t)(tid - 64) * 16, in + (size_t)n * 256 + (tid - 64) * 4);
    asm volatile("cp.async.commit_group;\n");
}

__global__ void __launch_bounds__(256, 2) attn2(const float* __restrict__ nb,
                                                const float* __restrict__ in) {
    extern __shared__ float dsm[];
    __shared__ float s_e[KNBR], s_rs[KNBR], s_veb[DIN];

    const int tid = threadIdx.x;
    const int lane = tid & 31;
    const int w = tid >> 5;
    const int nbase = blockIdx.x * ATTN_NPER;
    const uint32_t sb = (uint32_t)__cvta_generic_to_shared(dsm);
    const float ceb = g_ceb;

    s_veb[tid] = g_veb[tid];

    attn_issue(sb, nb, in, nbase + 0, 0, tid);
    attn_issue(sb, nb, in, nbase + 1, 1, tid);

    for (int j = 0; j < ATTN_NPER; ++j) {
        const int n = nbase + j;
        if (j + 2 < ATTN_NPER) {
            attn_issue(sb, nb, in, n + 2, (j + 2) % 3, tid);
            asm volatile("cp.async.wait_group 2;\n");
        } else if (j + 1 < ATTN_NPER) {
            asm volatile("cp.async.wait_group 1;\n");
        } else {
            asm volatile("cp.async.wait_group 0;\n");
        }
        __syncthreads();

        const float* bp  = dsm + (j % 3) * STG_F;
        const float* qb  = bp + 8192;
        const float* inp = bp + 8448;

        // ebv (warp-redundant): input[n] . veb + ceb
        float p = 0.f;
#pragma unroll
        for (int m = 0; m < 8; ++m)
            p += inp[lane + 32 * m] * s_veb[lane + 32 * m];
#pragma unroll
        for (int o = 16; o; o >>= 1) p += __shfl_xor_sync(0xffffffffu, p, o);
        const float ebv = p + ceb;

        // energies + row sums: warp w -> k = 4w..4w+3
#pragma unroll
        for (int kk = 0; kk < 4; ++kk) {
            const int k = w * 4 + kk;
            float e = 0.f, rs = 0.f;
#pragma unroll
            for (int m = 0; m < 8; ++m) {
                float v = bp[k * DIN + lane + 32 * m];
                rs += v;
                e += v * qb[lane + 32 * m];
            }
#pragma unroll
            for (int o = 16; o; o >>= 1) {
                e  += __shfl_xor_sync(0xffffffffu, e, o);
                rs += __shfl_xor_sync(0xffffffffu, rs, o);
            }
            if (lane == 0) { s_e[k] = e; s_rs[k] = rs; }
        }
        __syncthreads();

        // softmax replicated per warp (att held in register, lane = k)
        float e = (s_rs[lane] == 0.0f) ? 1e-12f : (s_e[lane] + ebv);
        float mx = e;
#pragma unroll
        for (int o = 16; o; o >>= 1) mx = fmaxf(mx, __shfl_xor_sync(0xffffffffu, mx, o));
        float ex = expf(e - mx);
        float sum = ex;
#pragma unroll
        for (int o = 16; o; o >>= 1) sum += __shfl_xor_sync(0xffffffffu, sum, o);
        const float att = ex / sum;

        // ctx[n, tid] = sum_k att[k] * nb[k, tid]
        float c = 0.f;
#pragma unroll
        for (int k = 0; k < KNBR; ++k)
            c += __shfl_sync(0xffffffffu, att, k) * bp[k * DIN + tid];
        __nv_bfloat16 h, l; bsplit(c, h, l);
        g_ctxh[(size_t)n * DIN + tid] = h;
        g_ctxl[(size_t)n * DIN + tid] = l;
        __syncthreads();   // all reads of buf (j%3) done before iter j+1 issues into it
    }
}

// ---------------- BN final (from GEMM-epilogue partials) ---------------------
__global__ void __launch_bounds__(512) bn_final() {
    const int c = threadIdx.x;
    float s = 0.f, sq = 0.f;
    for (int b = 0; b < 128; ++b) {
        s  += g_part[(b * 512 + c) * 2 + 0];
        sq += g_part[(b * 512 + c) * 2 + 1];
    }
    const float inv = 1.0f / (float)NROWS;
    float mean = s * inv;
    float var = sq * inv - mean * mean;
    g_mean[c] = mean;
    g_scale[c] = rsqrtf(var + 1e-5f);
}

// ---------------- host launch ------------------------------------------------
extern "C" void kernel_launch(void* const* d_in, const int* in_sizes, int n_in,
                              void* d_out, int out_size) {
    (void)in_sizes; (void)n_in; (void)out_size;
    const float* input = (const float*)d_in[0];
    const float* nb    = (const float*)d_in[1];
    const float* Wq    = (const float*)d_in[2];
    const float* bq    = (const float*)d_in[3];
    const float* Wk    = (const float*)d_in[4];
    const float* bk    = (const float*)d_in[5];
    const float* Wv    = (const float*)d_in[6];
    const float* bv    = (const float*)d_in[7];
    const float* Wno   = (const float*)d_in[8];
    const float* bno   = (const float*)d_in[9];
    const float* Wio   = (const float*)d_in[10];
    const float* bio   = (const float*)d_in[11];
    const float* Wg    = (const float*)d_in[12];
    const float* bg    = (const float*)d_in[13];
    const float* gamma = (const float*)d_in[14];
    const float* beta  = (const float*)d_in[15];
    float* out = (float*)d_out;

    __nv_bfloat16 *p_inh, *p_inl, *p_Mth, *p_Mtl, *p_Wioh, *p_Wiol;
    __nv_bfloat16 *p_Wnvh, *p_Wnvl, *p_Wgh, *p_Wgl, *p_ctxh, *p_ctxl, *p_o2h, *p_o2l;
    float *p_bqk, *p_bnv, *p_qt;
    cudaGetSymbolAddress((void**)&p_inh,  g_inh);
    cudaGetSymbolAddress((void**)&p_inl,  g_inl);
    cudaGetSymbolAddress((void**)&p_Mth,  g_Mth);
    cudaGetSymbolAddress((void**)&p_Mtl,  g_Mtl);
    cudaGetSymbolAddress((void**)&p_Wioh, g_Wioh);
    cudaGetSymbolAddress((void**)&p_Wiol, g_Wiol);
    cudaGetSymbolAddress((void**)&p_Wnvh, g_Wnvh);
    cudaGetSymbolAddress((void**)&p_Wnvl, g_Wnvl);
    cudaGetSymbolAddress((void**)&p_Wgh,  g_Wgh);
    cudaGetSymbolAddress((void**)&p_Wgl,  g_Wgl);
    cudaGetSymbolAddress((void**)&p_ctxh, g_ctxh);
    cudaGetSymbolAddress((void**)&p_ctxl, g_ctxl);
    cudaGetSymbolAddress((void**)&p_o2h,  g_o2h);
    cudaGetSymbolAddress((void**)&p_o2l,  g_o2l);
    cudaGetSymbolAddress((void**)&p_bqk,  g_bqk);
    cudaGetSymbolAddress((void**)&p_bnv,  g_bnv);
    cudaGetSymbolAddress((void**)&p_qt,   g_qt);

    cudaFuncSetAttribute(bmma_gemm<0>, cudaFuncAttributeMaxDynamicSharedMemorySize, 81920);
    cudaFuncSetAttribute(bmma_gemm<1>, cudaFuncAttributeMaxDynamicSharedMemorySize, 81920);
    cudaFuncSetAttribute(bmma_gemm<2>, cudaFuncAttributeMaxDynamicSharedMemorySize, 81920);
    cudaFuncSetAttribute(attn2,        cudaFuncAttributeMaxDynamicSharedMemorySize, 3 * STG_B);
    const int SMEM = 81920;

    prep_all<<<516, 256>>>(Wq, Wk, Wno, Wv, bq, bk, bv, bno);                 // 0
    split_all<<<4416, 256>>>(input, Wio, Wg);                                 // 1

    // qt = input @ Mt^T + bqk
    bmma_gemm<0><<<dim3(2, 128), 256, SMEM>>>(p_inh, p_inl, p_Mth, p_Mtl,     // 2
                                              p_bqk, p_qt, 256, 256, 0,
                                              nullptr, nullptr, nullptr);
    // self_out -> o2 cols [0,256)                     [profiled slot: index 3]
    bmma_gemm<1><<<dim3(2, 128), 256, SMEM>>>(p_inh, p_inl, p_Wioh, p_Wiol,   // 3
                                              bio, nullptr, 256, 512, 0,
                                              nullptr, nullptr, nullptr);
    // fused pipelined attention -> ctx (bf16 hi/lo)
    attn2<<<2048, 256, 3 * STG_B>>>(nb, input);                               // 4

    // neigh_out = ctx @ Wnv^T + bnv -> o2 cols [256,512)
    bmma_gemm<1><<<dim3(2, 128), 256, SMEM>>>(p_ctxh, p_ctxl, p_Wnvh, p_Wnvl, // 5
                                              p_bnv, nullptr, 256, 512, 256,
                                              nullptr, nullptr, nullptr);
    bn_final<<<1, 512>>>();                                                   // 6

    // gate GEMM fused with final: out = relu(o2@Wg^T+bg) * relu(bn(o2))
    bmma_gemm<2><<<dim3(4, 128), 256, SMEM>>>(p_o2h, p_o2l, p_Wgh, p_Wgl,     // 7
                                              bg, nullptr, 512, 512, 0,
                                              gamma, beta, out);
}

// round 16
// speedup vs baseline: 1.0969x; 1.0969x over previous
#include <cuda_runtime.h>
#include <cuda_bf16.h>
#include <cstdint>

#define NROWS 16384
#define KNBR  32
#define DIN   256
#define DCAT  512

// ---------------- scratch (no allocation allowed -> device globals) ----------
__device__ __nv_bfloat16 g_inh[NROWS * 256], g_inl[NROWS * 256];
__device__ __nv_bfloat16 g_Mth[256 * 256],  g_Mtl[256 * 256];
__device__ __nv_bfloat16 g_Wioh[256 * 256], g_Wiol[256 * 256];
__device__ __nv_bfloat16 g_Wnvh[256 * 256], g_Wnvl[256 * 256];
__device__ __nv_bfloat16 g_ctxh[NROWS * 256], g_ctxl[NROWS * 256];
__device__ float g_out2[NROWS * 512];      // concat(self, neigh) fp32
__device__ float g_bqk[256];               // (Wk^T bq)
__device__ float g_veb[256];               // (Wq^T bk)
__device__ float g_bnv[256];               // Wno@bv + bno
__device__ float g_ceb;                    // bq . bk
__device__ float g_qt[NROWS * 256];        // input @ Mt^T + bqk   (fp32)
__device__ float g_part[128 * 512 * 2];    // BN partial sums
__device__ float g_mean[512];
__device__ float g_scale[512];

// ---------------- streams/events for capture-fork (created pre-baseline) -----
struct GbInit {
    cudaStream_t s2;
    cudaEvent_t ev[4];
    GbInit() {
        cudaStreamCreateWithFlags(&s2, cudaStreamNonBlocking);
        for (int i = 0; i < 4; ++i)
            cudaEventCreateWithFlags(&ev[i], cudaEventDisableTiming);
    }
};
static GbInit gbi;

// ---------------- helpers -----------------------------------------------------
__device__ __forceinline__ void bsplit(float x, __nv_bfloat16& h, __nv_bfloat16& l) {
    h = __float2bfloat16_rn(x);
    l = __float2bfloat16_rn(x - __bfloat162float(h));
}
__device__ __forceinline__ uint32_t packbf2(__nv_bfloat16 a, __nv_bfloat16 b) {
    __nv_bfloat162 p(a, b);
    return *reinterpret_cast<uint32_t*>(&p);
}
__device__ __forceinline__ void cp16(uint32_t s, const void* g) {
    asm volatile("cp.async.cg.shared.global [%0], [%1], 16;\n" :: "r"(s), "l"(g));
}
__device__ __forceinline__ void mma16816(float* c, const uint32_t* a, const uint32_t* b) {
    asm volatile(
        "mma.sync.aligned.m16n8k16.row.col.f32.bf16.bf16.f32 "
        "{%0,%1,%2,%3},{%4,%5,%6,%7},{%8,%9},{%0,%1,%2,%3};\n"
        : "+f"(c[0]), "+f"(c[1]), "+f"(c[2]), "+f"(c[3])
        : "r"(a[0]), "r"(a[1]), "r"(a[2]), "r"(a[3]), "r"(b[0]), "r"(b[1]));
}
__device__ __forceinline__ void ldsm4(uint32_t addr, uint32_t& r0, uint32_t& r1,
                                      uint32_t& r2, uint32_t& r3) {
    asm volatile("ldmatrix.sync.aligned.m8n8.x4.shared.b16 {%0,%1,%2,%3}, [%4];"
                 : "=r"(r0), "=r"(r1), "=r"(r2), "=r"(r3) : "r"(addr));
}
__device__ __forceinline__ uint32_t f2tf32(uint32_t x) {
    uint32_t r;
    asm("cvt.rna.tf32.f32 %0, %1;" : "=r"(r) : "r"(x));
    return r;
}

// ---------------- prep: fold weights + biases (bf16 hi/lo) -------------------
__global__ void prep_all(const float* __restrict__ Wq, const float* __restrict__ Wk,
                         const float* __restrict__ Wno, const float* __restrict__ Wv,
                         const float* __restrict__ bq, const float* __restrict__ bk,
                         const float* __restrict__ bv, const float* __restrict__ bno) {
    int b = blockIdx.x, t = threadIdx.x;
    if (b < 256) {
        int i = b; float acc = 0.f;
        for (int o = 0; o < 256; ++o) acc += Wk[o * 256 + i] * Wq[o * 256 + t];
        __nv_bfloat16 h, l; bsplit(acc, h, l);
        g_Mth[i * 256 + t] = h; g_Mtl[i * 256 + t] = l;
    } else if (b < 512) {
        int o = b - 256; float acc = 0.f;
        for (int d = 0; d < 256; ++d) acc += Wno[o * 256 + d] * Wv[d * 256 + t];
        __nv_bfloat16 h, l; bsplit(acc, h, l);
        g_Wnvh[o * 256 + t] = h; g_Wnvl[o * 256 + t] = l;
    } else if (b == 512) {
        float a = 0.f;
        for (int o = 0; o < 256; ++o) a += bq[o] * Wk[o * 256 + t];
        g_bqk[t] = a;
    } else if (b == 513) {
        float a = 0.f;
        for (int o = 0; o < 256; ++o) a += bk[o] * Wq[o * 256 + t];
        g_veb[t] = a;
    } else if (b == 514) {
        float a = 0.f;
        for (int d = 0; d < 256; ++d) a += Wno[t * 256 + d] * bv[d];
        g_bnv[t] = a + bno[t];
    } else if (t == 0) {
        float a = 0.f;
        for (int o = 0; o < 256; ++o) a += bq[o] * bk[o];
        g_ceb = a;
    }
}

// ---------------- split input / Wio into bf16 hi+lo --------------------------
__global__ void __launch_bounds__(256) split_all(const float* __restrict__ in,
                                                 const float* __restrict__ wio) {
    const int b = blockIdx.x, t = threadIdx.x;
    const float* src; __nv_bfloat16 *dh, *dl; int idx;
    if (b < 4096) { src = in;  dh = g_inh;  dl = g_inl;  idx = b * 256 + t; }
    else          { src = wio; dh = g_Wioh; dl = g_Wiol; idx = (b - 4096) * 256 + t; }
    float4 v = ((const float4*)src)[idx];
    __nv_bfloat16 h0, l0, h1, l1, h2, l2, h3, l3;
    bsplit(v.x, h0, l0); bsplit(v.y, h1, l1);
    bsplit(v.z, h2, l2); bsplit(v.w, h3, l3);
    uint2 H, L;
    H.x = packbf2(h0, h1); H.y = packbf2(h2, h3);
    L.x = packbf2(l0, l1); L.y = packbf2(l2, l3);
    ((uint2*)dh)[idx] = H;
    ((uint2*)dl)[idx] = L;
}

// ---------------- bf16x3 tensor-core GEMM (ldmatrix) -------------------------
// MODE 0: fp32 C. MODE 1: fp32 C + BN column partials.
template <int MODE>
__global__ void __launch_bounds__(256, 2) bmma_gemm(
    const __nv_bfloat16* __restrict__ Ah, const __nv_bfloat16* __restrict__ Al,
    const __nv_bfloat16* __restrict__ Wh, const __nv_bfloat16* __restrict__ Wl,
    const float* __restrict__ bias, float* __restrict__ C,
    int K, int ldc, int coff)
{
    extern __shared__ uint32_t sm[];   // [2 stages][Ah|Al|Wh|Wl], tile=128x20 u32

    const int tid = threadIdx.x;
    const int lane = tid & 31, warp = tid >> 5;
    const int wm = warp >> 2, wn = warp & 3;
    const int g = lane >> 2, tg = lane & 3;
    const int m0 = blockIdx.y * 128, n0 = blockIdx.x * 128;
    const uint32_t sbase = (uint32_t)__cvta_generic_to_shared(sm);

    const int lr = lane & 7;
    const int lh = (lane >> 3) & 1;
    const int lq = (lane >> 4) & 1;
    uint32_t aAddr[4];
#pragma unroll
    for (int mf = 0; mf < 4; ++mf) {
        const int row = wm * 64 + mf * 16 + lr + lh * 8;
        aAddr[mf] = sbase + 4u * (row * 20 + lq * 4);
    }
    uint32_t bAddr[2];
#pragma unroll
    for (int p = 0; p < 2; ++p) {
        const int row = wn * 32 + (2 * p + lq) * 8 + lr;
        bAddr[p] = sbase + 4u * (5120 + row * 20 + lh * 4);
    }

    float acc[4][4][4];
#pragma unroll
    for (int i = 0; i < 4; ++i)
#pragma unroll
        for (int j = 0; j < 4; ++j)
#pragma unroll
            for (int h = 0; h < 4; ++h) acc[i][j][h] = 0.f;

    const int nt = K >> 5;

#define ISSUE_TILE(T, BUF)                                                         \
    {                                                                              \
        _Pragma("unroll")                                                          \
        for (int i = 0; i < 2; ++i) {                                              \
            const int id = tid + 256 * i;                                          \
            const int r = id >> 2, cc = id & 3;                                    \
            const uint32_t drow = (uint32_t)(r * 80 + cc * 16 + (BUF) * 40960);    \
            const size_t acol = (size_t)(T) * 32 + cc * 8;                         \
            cp16(sbase + drow,         Ah + (size_t)(m0 + r) * K + acol);          \
            cp16(sbase + drow + 10240, Al + (size_t)(m0 + r) * K + acol);          \
            cp16(sbase + drow + 20480, Wh + (size_t)(n0 + r) * K + acol);          \
            cp16(sbase + drow + 30720, Wl + (size_t)(n0 + r) * K + acol);          \
        }                                                                          \
        asm volatile("cp.async.commit_group;\n");                                  \
    }

    ISSUE_TILE(0, 0);
    asm volatile("cp.async.wait_group 0;\n");
    __syncthreads();

    for (int t = 0; t < nt; ++t) {
        const int buf = t & 1;
        if (t + 1 < nt) ISSUE_TILE(t + 1, buf ^ 1);
        const uint32_t stg = (uint32_t)buf * 40960u;
#pragma unroll
        for (int ks = 0; ks < 2; ++ks) {
            const uint32_t koff = stg + 32u * ks;
            uint32_t bh[4][2], bl[4][2];
            ldsm4(bAddr[0] + koff,          bh[0][0], bh[0][1], bh[1][0], bh[1][1]);
            ldsm4(bAddr[1] + koff,          bh[2][0], bh[2][1], bh[3][0], bh[3][1]);
            ldsm4(bAddr[0] + koff + 10240u, bl[0][0], bl[0][1], bl[1][0], bl[1][1]);
            ldsm4(bAddr[1] + koff + 10240u, bl[2][0], bl[2][1], bl[3][0], bl[3][1]);
#pragma unroll
            for (int mf = 0; mf < 4; ++mf) {
                uint32_t ah[4], al[4];
                ldsm4(aAddr[mf] + koff,          ah[0], ah[1], ah[2], ah[3]);
                ldsm4(aAddr[mf] + koff + 10240u, al[0], al[1], al[2], al[3]);
#pragma unroll
                for (int nf = 0; nf < 4; ++nf)
                    mma16816(acc[mf][nf], ah, bh[nf]);
#pragma unroll
                for (int nf = 0; nf < 4; ++nf)
                    mma16816(acc[mf][nf], al, bh[nf]);
#pragma unroll
                for (int nf = 0; nf < 4; ++nf)
                    mma16816(acc[mf][nf], ah, bl[nf]);
            }
        }
        if (t + 1 < nt) {
            asm volatile("cp.async.wait_group 0;\n");
            __syncthreads();
        }
    }
#undef ISSUE_TILE

    // ---------------- epilogue ----------------
    float ps[4][2], pq[4][2];
#pragma unroll
    for (int nf = 0; nf < 4; ++nf) { ps[nf][0]=ps[nf][1]=pq[nf][0]=pq[nf][1]=0.f; }

#pragma unroll
    for (int mf = 0; mf < 4; ++mf) {
        const int r0 = m0 + wm * 64 + mf * 16 + g;
#pragma unroll
        for (int nf = 0; nf < 4; ++nf) {
            const int c = n0 + wn * 32 + nf * 8 + 2 * tg;
            const float b0 = bias[c], b1 = bias[c + 1];
#pragma unroll
            for (int h = 0; h < 2; ++h) {
                const int r = r0 + 8 * h;
                float v0 = acc[mf][nf][2 * h + 0] + b0;
                float v1 = acc[mf][nf][2 * h + 1] + b1;
                *(float2*)&C[(size_t)r * ldc + coff + c] = make_float2(v0, v1);
                if (MODE == 1) {
                    ps[nf][0] += v0; ps[nf][1] += v1;
                    pq[nf][0] += v0 * v0; pq[nf][1] += v1 * v1;
                }
            }
        }
    }

    if (MODE == 1) {
        __syncthreads();
        float* sbn = (float*)sm;   // [2 wm][128 col][2]
#pragma unroll
        for (int nf = 0; nf < 4; ++nf)
#pragma unroll
            for (int j = 0; j < 2; ++j) {
                float s = ps[nf][j], q = pq[nf][j];
#pragma unroll
                for (int o = 4; o < 32; o <<= 1) {
                    s += __shfl_xor_sync(0xffffffffu, s, o);
                    q += __shfl_xor_sync(0xffffffffu, q, o);
                }
                if (g == 0) {
                    const int col = wn * 32 + nf * 8 + 2 * tg + j;
                    sbn[(wm * 128 + col) * 2 + 0] = s;
                    sbn[(wm * 128 + col) * 2 + 1] = q;
                }
            }
        __syncthreads();
        if (tid < 256) {
            const int col = tid >> 1, q = tid & 1;
            const float tot = sbn[col * 2 + q] + sbn[(128 + col) * 2 + q];
            g_part[((size_t)(m0 >> 7) * 512 + coff + n0 + col) * 2 + q] = tot;
        }
    }
}

// ---------------- tf32 gate GEMM + fused final epilogue (from round 2) -------
// out = relu(out2 @ Wg^T + bg) * relu(bn(out2)),  K = 512.
__global__ void __launch_bounds__(256, 2) tf32_gate(
    const float* __restrict__ A, const float* __restrict__ W,
    const float* __restrict__ bias,
    const float* __restrict__ gamma, const float* __restrict__ beta,
    float* __restrict__ outp, int K)
{
    extern __shared__ uint32_t sm[];       // As[2][8][128]pad36 | Ws[2][8][128]pad36
    const int tid = threadIdx.x;
    const int lane = tid & 31, warp = tid >> 5;
    const int wm = warp >> 2, wn = warp & 3;
    const int g = lane >> 2, tg = lane & 3;
    const int m0 = blockIdx.y * 128, n0 = blockIdx.x * 128;

    const int rL = tid >> 3;
    const int cL = (tid & 7) * 4;
    const float* Agp = A + (size_t)(m0 + rL) * K + cL;
    const float* Wgp = W + (size_t)(n0 + rL) * K + cL;
    const uint32_t sbase = (uint32_t)__cvta_generic_to_shared(sm);

    float acc[4][4][4];
#pragma unroll
    for (int i = 0; i < 4; ++i)
#pragma unroll
        for (int j = 0; j < 4; ++j)
#pragma unroll
            for (int h = 0; h < 4; ++h) acc[i][j][h] = 0.f;

    const int nt = K >> 5;

#define G_ISSUE(T, BUF)                                                             \
    {                                                                               \
        _Pragma("unroll")                                                           \
        for (int i = 0; i < 4; ++i) {                                               \
            int rr = rL + 32 * i;                                                   \
            cp16(sbase + 4u * ((BUF) * 4608 + rr * 36 + cL),                        \
                 Agp + (size_t)32 * i * K + (T) * 32);                              \
            cp16(sbase + 4u * (9216 + (BUF) * 4608 + rr * 36 + cL),                 \
                 Wgp + (size_t)32 * i * K + (T) * 32);                              \
        }                                                                           \
        asm volatile("cp.async.commit_group;\n");                                   \
    }

    G_ISSUE(0, 0);
    asm volatile("cp.async.wait_group 0;\n");
    __syncthreads();

    for (int t = 0; t < nt; ++t) {
        const int cur = t & 1;
        if (t + 1 < nt) G_ISSUE(t + 1, cur ^ 1);
        const uint32_t* Ab = sm + cur * 4608;
        const uint32_t* Wb = sm + 9216 + cur * 4608;
#pragma unroll
        for (int ks = 0; ks < 4; ++ks) {
            const int kk = ks * 8;
            uint32_t a[4][4], b[4][2];
#pragma unroll
            for (int mf = 0; mf < 4; ++mf) {
                const int r = wm * 64 + mf * 16 + g;
                a[mf][0] = f2tf32(Ab[r * 36 + kk + tg]);
                a[mf][1] = f2tf32(Ab[(r + 8) * 36 + kk + tg]);
                a[mf][2] = f2tf32(Ab[r * 36 + kk + tg + 4]);
                a[mf][3] = f2tf32(Ab[(r + 8) * 36 + kk + tg + 4]);
            }
#pragma unroll
            for (int nf = 0; nf < 4; ++nf) {
                const int c = wn * 32 + nf * 8 + g;
                b[nf][0] = f2tf32(Wb[c * 36 + kk + tg]);
                b[nf][1] = f2tf32(Wb[c * 36 + kk + tg + 4]);
            }
#pragma unroll
            for (int mf = 0; mf < 4; ++mf)
#pragma unroll
                for (int nf = 0; nf < 4; ++nf)
                    asm volatile(
                        "mma.sync.aligned.m16n8k8.row.col.f32.tf32.tf32.f32 "
                        "{%0,%1,%2,%3},{%4,%5,%6,%7},{%8,%9},{%0,%1,%2,%3};\n"
                        : "+f"(acc[mf][nf][0]), "+f"(acc[mf][nf][1]),
                          "+f"(acc[mf][nf][2]), "+f"(acc[mf][nf][3])
                        : "r"(a[mf][0]), "r"(a[mf][1]), "r"(a[mf][2]), "r"(a[mf][3]),
                          "r"(b[nf][0]), "r"(b[nf][1]));
        }
        if (t + 1 < nt) {
            asm volatile("cp.async.wait_group 0;\n");
            __syncthreads();
        }
    }
#undef G_ISSUE

    // fused final epilogue
#pragma unroll
    for (int mf = 0; mf < 4; ++mf) {
        const int r0 = m0 + wm * 64 + mf * 16 + g;
#pragma unroll
        for (int nf = 0; nf < 4; ++nf) {
            const int c = n0 + wn * 32 + nf * 8 + 2 * tg;
#pragma unroll
            for (int h = 0; h < 2; ++h) {
                const int r = r0 + 8 * h;
                float2 res;
#pragma unroll
                for (int j = 0; j < 2; ++j) {
                    const int cc = c + j;
                    float pre = acc[mf][nf][2 * h + j] + bias[cc];
                    float o = g_out2[(size_t)r * 512 + cc];
                    float bnv = gamma[cc] * (o - g_mean[cc]) * g_scale[cc] + beta[cc];
                    float v = fmaxf(pre, 0.f) * fmaxf(bnv, 0.f);
                    if (j == 0) res.x = v; else res.y = v;
                }
                *(float2*)&outp[(size_t)r * 512 + c] = res;
            }
        }
    }
}

// ---------------- pipelined attention: 8 n/CTA, 3-stage cp.async -------------
#define ATTN_NPER 8
#define STG_F 8704
#define STG_B 34816

__device__ __forceinline__ void attn_issue(uint32_t sb, const float* __restrict__ nb,
                                           const float* __restrict__ in,
                                           int n, int buf, int tid) {
    const uint32_t base = sb + (uint32_t)buf * STG_B;
    const float* src = nb + (size_t)n * 8192 + tid * 4;
#pragma unroll
    for (int i = 0; i < 8; ++i)
        cp16(base + (uint32_t)tid * 16 + i * 4096, src + i * 1024);
    if (tid < 64)
        cp16(base + 32768 + (uint32_t)tid * 16, g_qt + (size_t)n * 256 + tid * 4);
    else if (tid < 128)
        cp16(base + 33792 + (uint32_t)(tid - 64) * 16, in + (size_t)n * 256 + (tid - 64) * 4);
    asm volatile("cp.async.commit_group;\n");
}

__global__ void __launch_bounds__(256, 2) attn2(const float* __restrict__ nb,
                                                const float* __restrict__ in) {
    extern __shared__ float dsm[];
    __shared__ float s_e[KNBR], s_rs[KNBR], s_veb[DIN];

    const int tid = threadIdx.x;
    const int lane = tid & 31;
    const int w = tid >> 5;
    const int nbase = blockIdx.x * ATTN_NPER;
    const uint32_t sb = (uint32_t)__cvta_generic_to_shared(dsm);
    const float ceb = g_ceb;

    s_veb[tid] = g_veb[tid];

    attn_issue(sb, nb, in, nbase + 0, 0, tid);
    attn_issue(sb, nb, in, nbase + 1, 1, tid);

    for (int j = 0; j < ATTN_NPER; ++j) {
        const int n = nbase + j;
        if (j + 2 < ATTN_NPER) {
            attn_issue(sb, nb, in, n + 2, (j + 2) % 3, tid);
            asm volatile("cp.async.wait_group 2;\n");
        } else if (j + 1 < ATTN_NPER) {
            asm volatile("cp.async.wait_group 1;\n");
        } else {
            asm volatile("cp.async.wait_group 0;\n");
        }
        __syncthreads();

        const float* bp  = dsm + (j % 3) * STG_F;
        const float* qb  = bp + 8192;
        const float* inp = bp + 8448;

        float p = 0.f;
#pragma unroll
        for (int m = 0; m < 8; ++m)
            p += inp[lane + 32 * m] * s_veb[lane + 32 * m];
#pragma unroll
        for (int o = 16; o; o >>= 1) p += __shfl_xor_sync(0xffffffffu, p, o);
        const float ebv = p + ceb;

#pragma unroll
        for (int kk = 0; kk < 4; ++kk) {
            const int k = w * 4 + kk;
            float e = 0.f, rs = 0.f;
#pragma unroll
            for (int m = 0; m < 8; ++m) {
                float v = bp[k * DIN + lane + 32 * m];
                rs += v;
                e += v * qb[lane + 32 * m];
            }
#pragma unroll
            for (int o = 16; o; o >>= 1) {
                e  += __shfl_xor_sync(0xffffffffu, e, o);
                rs += __shfl_xor_sync(0xffffffffu, rs, o);
            }
            if (lane == 0) { s_e[k] = e; s_rs[k] = rs; }
        }
        __syncthreads();

        float e = (s_rs[lane] == 0.0f) ? 1e-12f : (s_e[lane] + ebv);
        float mx = e;
#pragma unroll
        for (int o = 16; o; o >>= 1) mx = fmaxf(mx, __shfl_xor_sync(0xffffffffu, mx, o));
        float ex = expf(e - mx);
        float sum = ex;
#pragma unroll
        for (int o = 16; o; o >>= 1) sum += __shfl_xor_sync(0xffffffffu, sum, o);
        const float att = ex / sum;

        float c = 0.f;
#pragma unroll
        for (int k = 0; k < KNBR; ++k)
            c += __shfl_sync(0xffffffffu, att, k) * bp[k * DIN + tid];
        __nv_bfloat16 h, l; bsplit(c, h, l);
        g_ctxh[(size_t)n * DIN + tid] = h;
        g_ctxl[(size_t)n * DIN + tid] = l;
        __syncthreads();
    }
}

// ---------------- BN final (from GEMM-epilogue partials) ---------------------
__global__ void __launch_bounds__(512) bn_final() {
    const int c = threadIdx.x;
    float s = 0.f, sq = 0.f;
    for (int b = 0; b < 128; ++b) {
        s  += g_part[(b * 512 + c) * 2 + 0];
        sq += g_part[(b * 512 + c) * 2 + 1];
    }
    const float inv = 1.0f / (float)NROWS;
    float mean = s * inv;
    float var = sq * inv - mean * mean;
    g_mean[c] = mean;
    g_scale[c] = rsqrtf(var + 1e-5f);
}

// ---------------- host launch ------------------------------------------------
extern "C" void kernel_launch(void* const* d_in, const int* in_sizes, int n_in,
                              void* d_out, int out_size) {
    (void)in_sizes; (void)n_in; (void)out_size;
    const float* input = (const float*)d_in[0];
    const float* nb    = (const float*)d_in[1];
    const float* Wq    = (const float*)d_in[2];
    const float* bq    = (const float*)d_in[3];
    const float* Wk    = (const float*)d_in[4];
    const float* bk    = (const float*)d_in[5];
    const float* Wv    = (const float*)d_in[6];
    const float* bv    = (const float*)d_in[7];
    const float* Wno   = (const float*)d_in[8];
    const float* bno   = (const float*)d_in[9];
    const float* Wio   = (const float*)d_in[10];
    const float* bio   = (const float*)d_in[11];
    const float* Wg    = (const float*)d_in[12];
    const float* bg    = (const float*)d_in[13];
    const float* gamma = (const float*)d_in[14];
    const float* beta  = (const float*)d_in[15];
    float* out = (float*)d_out;

    __nv_bfloat16 *p_inh, *p_inl, *p_Mth, *p_Mtl, *p_Wioh, *p_Wiol;
    __nv_bfloat16 *p_Wnvh, *p_Wnvl, *p_ctxh, *p_ctxl;
    float *p_bqk, *p_bnv, *p_qt, *p_out2;
    cudaGetSymbolAddress((void**)&p_inh,  g_inh);
    cudaGetSymbolAddress((void**)&p_inl,  g_inl);
    cudaGetSymbolAddress((void**)&p_Mth,  g_Mth);
    cudaGetSymbolAddress((void**)&p_Mtl,  g_Mtl);
    cudaGetSymbolAddress((void**)&p_Wioh, g_Wioh);
    cudaGetSymbolAddress((void**)&p_Wiol, g_Wiol);
    cudaGetSymbolAddress((void**)&p_Wnvh, g_Wnvh);
    cudaGetSymbolAddress((void**)&p_Wnvl, g_Wnvl);
    cudaGetSymbolAddress((void**)&p_ctxh, g_ctxh);
    cudaGetSymbolAddress((void**)&p_ctxl, g_ctxl);
    cudaGetSymbolAddress((void**)&p_bqk,  g_bqk);
    cudaGetSymbolAddress((void**)&p_bnv,  g_bnv);
    cudaGetSymbolAddress((void**)&p_qt,   g_qt);
    cudaGetSymbolAddress((void**)&p_out2, g_out2);

    cudaFuncSetAttribute(bmma_gemm<0>, cudaFuncAttributeMaxDynamicSharedMemorySize, 81920);
    cudaFuncSetAttribute(bmma_gemm<1>, cudaFuncAttributeMaxDynamicSharedMemorySize, 81920);
    cudaFuncSetAttribute(tf32_gate,    cudaFuncAttributeMaxDynamicSharedMemorySize, 73728);
    cudaFuncSetAttribute(attn2,        cudaFuncAttributeMaxDynamicSharedMemorySize, 3 * STG_B);
    const int SMEM = 81920;

    // fork: split on s2 overlaps prep on stream 0
    cudaEventRecord(gbi.ev[0], 0);
    cudaStreamWaitEvent(gbi.s2, gbi.ev[0], 0);
    split_all<<<4160, 256, 0, gbi.s2>>>(input, Wio);
    prep_all<<<516, 256>>>(Wq, Wk, Wno, Wv, bq, bk, bv, bno);

    // join: qt needs split output
    cudaEventRecord(gbi.ev[1], gbi.s2);
    cudaStreamWaitEvent(0, gbi.ev[1], 0);

    // qt = input @ Mt^T + bqk   (stream 0)
    bmma_gemm<0><<<dim3(2, 128), 256, SMEM>>>(p_inh, p_inl, p_Mth, p_Mtl,
                                              p_bqk, p_qt, 256, 256, 0);

    // fork: self GEMM on s2 runs concurrently with attention
    cudaEventRecord(gbi.ev[2], 0);
    cudaStreamWaitEvent(gbi.s2, gbi.ev[2], 0);
    bmma_gemm<1><<<dim3(2, 128), 256, SMEM, gbi.s2>>>(p_inh, p_inl, p_Wioh, p_Wiol,
                                                      bio, p_out2, 256, 512, 0);

    // attention (stream 0, the long pole)
    attn2<<<2048, 256, 3 * STG_B>>>(nb, input);

    // neigh_out = ctx @ Wnv^T + bnv  (stream 0, after attn)
    bmma_gemm<1><<<dim3(2, 128), 256, SMEM>>>(p_ctxh, p_ctxl, p_Wnvh, p_Wnvl,
                                              p_bnv, p_out2, 256, 512, 256);

    // join: bn needs self's BN partials too
    cudaEventRecord(gbi.ev[3], gbi.s2);
    cudaStreamWaitEvent(0, gbi.ev[3], 0);
    bn_final<<<1, 512>>>();

    // gate GEMM (tf32) fused with final epilogue
    tf32_gate<<<dim3(4, 128), 256, 73728>>>(p_out2, Wg, bg, gamma, beta, out, 512);
}